// round 11
// baseline (speedup 1.0000x reference)
#include <cuda_runtime.h>
#include <math.h>

#define NN 65536
#define EE 1048576
#define BB 256

// ---------------- device scratch (static globals; no allocation) ----------------
__device__ __align__(16) float g_h[NN * 64];      // node state h
__device__ __align__(16) float g_hB[NN * 64];     // ping-pong buffer
__device__ __align__(16) float g_gix[NN * 192];   // W_ih[:,64:96]@x + b_ih
__device__ __align__(16) float g_Wx2[256 * 32];   // [o][k] o<64: W_mlp ; o>=64: W_ih x-part
__device__ float g_bx[256];
// GRU weights, [k][192] layout for coalesced smem staging
__device__ __align__(16) float g_WgA[64 * 192];   // Wcomb = W_ih_m @ W_conv (r,z,n)
__device__ __align__(16) float g_WgH[64 * 192];   // W_hh (r,z,n)
__device__ float g_bvec[192];                     // W_ih_m @ b_conv
// transposed Set2Set/head weights (coalesced: k-major)
__device__ __align__(16) float g_lWihT[128 * 256];
__device__ __align__(16) float g_lWhhT[64 * 256];
__device__ __align__(16) float g_W1T[128 * 64];
// CSR
__device__ int g_cnt[NN];
__device__ int g_off[NN];
__device__ int g_cur[NN];
__device__ float g_degf[NN];
__device__ int g_bsum[256];
__device__ int g_bpre[256];
__device__ int g_csr[EE];
// batch / graph ranges
__device__ int g_bhist[256];
__device__ int g_gbeg[257];
__device__ int g_is64e, g_is64b;

__device__ __forceinline__ float sigm(float x) { return 1.0f / (1.0f + expf(-x)); }

// packed fp32x2 fma (sm_103a)
__device__ __forceinline__ void ffma2(unsigned long long& d, unsigned long long a, unsigned long long b) {
    asm("fma.rn.f32x2 %0, %1, %2, %3;" : "=l"(d) : "l"(a), "l"(b), "l"(d));
}
__device__ __forceinline__ unsigned long long packdup(float x) {
    unsigned long long r;
    asm("mov.b64 %0, {%1, %1};" : "=l"(r) : "f"(x));
    return r;
}
__device__ __forceinline__ float lo2(unsigned long long v) { return __uint_as_float((unsigned)(v & 0xffffffffull)); }
__device__ __forceinline__ float hi2(unsigned long long v) { return __uint_as_float((unsigned)(v >> 32)); }

__device__ __forceinline__ int ld_idx(const int* p, int i, int is64) {
    return is64 ? p[2 * i] : p[i];
}

// ---------------- fused prep: dtype detect + all weight re-layouts + zeroing ----------------
__global__ void k_prepB(const float* W_mlp, const float* b_mlp,
                        const float* W_ih, const float* b_ih,
                        const float* W_hh, const float* W_conv, const float* b_conv,
                        const float* lWih, const float* lWhh, const float* W1,
                        const int* ei, const int* bt) {
    // warp-parallel dtype detection (block 0, warp 0)
    if (blockIdx.x == 0 && threadIdx.x < 32) {
        int lane = threadIdx.x;
        int v  = ei[2 * EE - 1 - 2 * lane];   // odd words near tail (int64 => 0)
        int vb = bt[NN - 1 - 2 * lane];       // batch sorted: tail ~ B-1 != 0 for int32
        unsigned m  = __ballot_sync(0xffffffffu, v != 0);
        unsigned mb = __ballot_sync(0xffffffffu, vb != 0);
        if (lane == 0) { g_is64e = (m == 0u) ? 1 : 0; g_is64b = (mb == 0u) ? 1 : 0; }
    }
    int t = blockIdx.x * blockDim.x + threadIdx.x;
    if (t < 8192) {
        int o = t >> 5, k = t & 31;
        g_Wx2[t] = (o < 64) ? W_mlp[o * 32 + k] : W_ih[(o - 64) * 96 + 64 + k];
    } else if (t < 8448) {
        int o = t - 8192;
        g_bx[o] = (o < 64) ? b_mlp[o] : b_ih[o - 64];
    } else if (t < 20736) {
        int u = t - 8448;
        int g = u >> 12, j = (u >> 6) & 63, k = u & 63;
        const float* wr = W_ih + (g * 64 + j) * 96;
        float v = 0.f;
#pragma unroll 8
        for (int o = 0; o < 64; o++) v += wr[o] * W_conv[o * 64 + k];
        g_WgA[k * 192 + g * 64 + j] = v;
    } else if (t < 33024) {
        int u = t - 20736;
        int g = u >> 12, j = (u >> 6) & 63, k = u & 63;
        g_WgH[k * 192 + g * 64 + j] = W_hh[(g * 64 + j) * 64 + k];
    } else if (t < 33216) {
        int o = t - 33024;
        const float* wr = W_ih + o * 96;
        float v = 0.f;
#pragma unroll 8
        for (int o2 = 0; o2 < 64; o2++) v += wr[o2] * b_conv[o2];
        g_bvec[o] = v;
    } else if (t < 49600) {
        ((int4*)g_cnt)[t - 33216] = make_int4(0, 0, 0, 0);
    } else if (t < 49856) {
        g_bhist[t - 49600] = 0;
    } else if (t < 82624) {
        int u = t - 49856;
        int k = u >> 8, o = u & 255;
        g_lWihT[k * 256 + o] = lWih[o * 128 + k];
    } else if (t < 99008) {
        int u = t - 82624;
        int k = u >> 8, o = u & 255;
        g_lWhhT[k * 256 + o] = lWhh[o * 64 + k];
    } else if (t < 107200) {
        int u = t - 99008;
        int k = u >> 6, o = u & 63;
        g_W1T[k * 64 + o] = W1[o * 128 + k];
    }
}

// ---------------- histograms: edge dst (CSR) + batch (graph ranges) ----------------
__global__ void k_hist(const int* ei, const int* bt) {
    int t = blockIdx.x * 256 + threadIdx.x;
    int dst = ld_idx(ei, EE + t, g_is64e);
    atomicAdd(&g_cnt[dst], 1);
    if (t < NN) {
        int b = ld_idx(bt, t, g_is64b);
        atomicAdd(&g_bhist[b], 1);
    }
}
__global__ void k_scan1() {
    __shared__ int s[256];
    int tid = threadIdx.x;
    int i = blockIdx.x * 256 + tid;
    int v = g_cnt[i];
    s[tid] = v; __syncthreads();
    for (int d = 1; d < 256; d <<= 1) {
        int t = (tid >= d) ? s[tid - d] : 0; __syncthreads();
        s[tid] += t; __syncthreads();
    }
    g_off[i] = s[tid] - v;
    if (tid == 255) g_bsum[blockIdx.x] = s[255];
}
__global__ void k_scan2() {
    __shared__ int s[256];
    int tid = threadIdx.x;
    int v = g_bsum[tid];
    s[tid] = v; __syncthreads();
    for (int d = 1; d < 256; d <<= 1) {
        int t = (tid >= d) ? s[tid - d] : 0; __syncthreads();
        s[tid] += t; __syncthreads();
    }
    g_bpre[tid] = s[tid] - v;
    __syncthreads();
    int vb = g_bhist[tid];
    s[tid] = vb; __syncthreads();
    for (int d = 1; d < 256; d <<= 1) {
        int t = (tid >= d) ? s[tid - d] : 0; __syncthreads();
        s[tid] += t; __syncthreads();
    }
    g_gbeg[tid] = s[tid] - vb;
    if (tid == 255) g_gbeg[256] = s[255];
}
__global__ void k_scan3() {
    int i = blockIdx.x * 256 + threadIdx.x;
    int off = g_off[i] + g_bpre[blockIdx.x];
    g_off[i] = off;
    g_cur[i] = off;
    g_degf[i] = (float)g_cnt[i];
}
__global__ void k_fill(const int* ei) {
    int e = blockIdx.x * 256 + threadIdx.x;
    int is64 = g_is64e;
    int src = ld_idx(ei, e, is64);
    int dst = ld_idx(ei, EE + e, is64);
    int p = atomicAdd(&g_cur[dst], 1);
    g_csr[p] = src;
}

// ---------------- node MLP + gix precompute: [N,32]@[32,256] ----------------
__global__ __launch_bounds__(256) void k_mlp2(const float* x) {
    int o = threadIdx.x;
    int nb = blockIdx.x * 16;
    const ulonglong2* Wp = (const ulonglong2*)(g_Wx2 + o * 32);
    ulonglong2 w[8];
#pragma unroll
    for (int kk = 0; kk < 8; kk++) w[kk] = __ldg(&Wp[kk]);
    float bias = g_bx[o];
#pragma unroll 2
    for (int i = 0; i < 16; i++) {
        int n = nb + i;
        const ulonglong2* xr = (const ulonglong2*)(x + (size_t)n * 32);
        unsigned long long a0 = 0ull, a1 = 0ull;
#pragma unroll
        for (int kk = 0; kk < 8; kk++) {
            ulonglong2 v = __ldg(&xr[kk]);
            ffma2(a0, v.x, w[kk].x);
            ffma2(a1, v.y, w[kk].y);
        }
        float v = lo2(a0) + hi2(a0) + lo2(a1) + hi2(a1) + bias;
        if (o < 64) g_h[(size_t)n * 64 + o] = v;
        else        g_gix[(size_t)n * 192 + (o - 64)] = v;
    }
}

// ---------------- fused gather + GRU step (conv-fused, smem-staged, f32x2) ----------------
// block = 64 nodes, 256 threads.
// Phase 0: stage Xh (coalesced) + gather neighbor sums directly into Xa (warp per node, 8/warp).
// Phase 1/2: gi = Wcomb@Xa, gh = W_hh@Xh with smem-staged weights; thread-local combine.
#define GRU_SMEM ((64 * 68 * 2 + 64 * 192) * 4)
__global__ __launch_bounds__(256) void k_gru4(int step, const float* b_hh) {
    const float* hin = step ? g_hB : g_h;
    float* hout      = step ? g_h  : g_hB;
    extern __shared__ float sm[];
    float* Xa = sm;                 // 64*68 (gathered neighbor sums)
    float* Xh = Xa + 64 * 68;       // 64*68 (own h)
    float* Ws = Xh + 64 * 68;       // 64*192 (weights; reused per phase)

    int tid = threadIdx.x;
    int nb = blockIdx.x * 64;
    int warp = tid >> 5, lane = tid & 31;

    // stage Xh + Wcomb (coalesced)
    for (int i = tid; i < 64 * 16; i += 256) {
        int n = i >> 4, kq = i & 15;
        *(float4*)&Xh[n * 68 + kq * 4] = *(const float4*)&hin[(size_t)(nb + n) * 64 + kq * 4];
    }
    for (int i = tid; i < 64 * 192 / 4; i += 256)
        ((float4*)Ws)[i] = ((const float4*)g_WgA)[i];

    // gather: warp w handles nodes nb + w*8 .. +8, lane covers float2 channel
    const float2* hb = (const float2*)hin;
#pragma unroll 1
    for (int i = 0; i < 8; i++) {
        int nloc = warp * 8 + i;
        int node = nb + nloc;
        int beg = g_off[node], cnt = g_cnt[node];
        float ax = 0.f, ay = 0.f;
        int t = 0;
        for (; t + 4 <= cnt; t += 4) {
            int s0 = __ldg(&g_csr[beg + t]);
            int s1 = __ldg(&g_csr[beg + t + 1]);
            int s2 = __ldg(&g_csr[beg + t + 2]);
            int s3 = __ldg(&g_csr[beg + t + 3]);
            float2 v0 = __ldg(&hb[(size_t)s0 * 32 + lane]);
            float2 v1 = __ldg(&hb[(size_t)s1 * 32 + lane]);
            float2 v2 = __ldg(&hb[(size_t)s2 * 32 + lane]);
            float2 v3 = __ldg(&hb[(size_t)s3 * 32 + lane]);
            ax += v0.x + v1.x + v2.x + v3.x;
            ay += v0.y + v1.y + v2.y + v3.y;
        }
        for (; t < cnt; t++) {
            int s = __ldg(&g_csr[beg + t]);
            float2 v = __ldg(&hb[(size_t)s * 32 + lane]);
            ax += v.x; ay += v.y;
        }
        float2 o; o.x = ax; o.y = ay;
        *(float2*)&Xa[nloc * 68 + lane * 2] = o;
    }
    __syncthreads();

    int tg = tid & 31;
    int tn = tid >> 5;
    const float* xa = Xa + (tn * 8) * 68;
    const float* xh = Xh + (tn * 8) * 68;

    unsigned long long gia[3][8], gha[3][8];
#pragma unroll
    for (int g = 0; g < 3; g++)
#pragma unroll
        for (int n = 0; n < 8; n++) { gia[g][n] = 0ull; gha[g][n] = 0ull; }

    // phase 1: gi = Wcomb @ agg
#pragma unroll 4
    for (int k = 0; k < 64; k++) {
        unsigned long long w0 = *(const unsigned long long*)&Ws[k * 192 + tg * 2];
        unsigned long long w1 = *(const unsigned long long*)&Ws[k * 192 + 64 + tg * 2];
        unsigned long long w2 = *(const unsigned long long*)&Ws[k * 192 + 128 + tg * 2];
#pragma unroll
        for (int n = 0; n < 8; n++) {
            unsigned long long xd = packdup(xa[n * 68 + k]);
            ffma2(gia[0][n], xd, w0);
            ffma2(gia[1][n], xd, w1);
            ffma2(gia[2][n], xd, w2);
        }
    }
    __syncthreads();
    for (int i = tid; i < 64 * 192 / 4; i += 256)
        ((float4*)Ws)[i] = ((const float4*)g_WgH)[i];
    __syncthreads();
    // phase 2: gh = W_hh @ h
#pragma unroll 4
    for (int k = 0; k < 64; k++) {
        unsigned long long w0 = *(const unsigned long long*)&Ws[k * 192 + tg * 2];
        unsigned long long w1 = *(const unsigned long long*)&Ws[k * 192 + 64 + tg * 2];
        unsigned long long w2 = *(const unsigned long long*)&Ws[k * 192 + 128 + tg * 2];
#pragma unroll
        for (int n = 0; n < 8; n++) {
            unsigned long long xd = packdup(xh[n * 68 + k]);
            ffma2(gha[0][n], xd, w0);
            ffma2(gha[1][n], xd, w1);
            ffma2(gha[2][n], xd, w2);
        }
    }

    int j0 = tg * 2;
    float2 bh_r = *(const float2*)&b_hh[j0];
    float2 bh_z = *(const float2*)&b_hh[64 + j0];
    float2 bh_n = *(const float2*)&b_hh[128 + j0];
    float2 bv_r = *(const float2*)&g_bvec[j0];
    float2 bv_z = *(const float2*)&g_bvec[64 + j0];
    float2 bv_n = *(const float2*)&g_bvec[128 + j0];
#pragma unroll
    for (int n = 0; n < 8; n++) {
        int node = nb + tn * 8 + n;
        float degf = g_degf[node];
        const float* gx = g_gix + (size_t)node * 192;
        float2 gx_r = *(const float2*)&gx[j0];
        float2 gx_z = *(const float2*)&gx[64 + j0];
        float2 gx_n = *(const float2*)&gx[128 + j0];

        float gir0 = lo2(gia[0][n]) + gx_r.x + degf * bv_r.x;
        float gir1 = hi2(gia[0][n]) + gx_r.y + degf * bv_r.y;
        float giz0 = lo2(gia[1][n]) + gx_z.x + degf * bv_z.x;
        float giz1 = hi2(gia[1][n]) + gx_z.y + degf * bv_z.y;
        float gin0 = lo2(gia[2][n]) + gx_n.x + degf * bv_n.x;
        float gin1 = hi2(gia[2][n]) + gx_n.y + degf * bv_n.y;
        float ghr0 = lo2(gha[0][n]) + bh_r.x;
        float ghr1 = hi2(gha[0][n]) + bh_r.y;
        float ghz0 = lo2(gha[1][n]) + bh_z.x;
        float ghz1 = hi2(gha[1][n]) + bh_z.y;
        float ghn0 = lo2(gha[2][n]) + bh_n.x;
        float ghn1 = hi2(gha[2][n]) + bh_n.y;

        float r0 = sigm(gir0 + ghr0), r1 = sigm(gir1 + ghr1);
        float z0 = sigm(giz0 + ghz0), z1 = sigm(giz1 + ghz1);
        float ng0 = tanhf(gin0 + r0 * ghn0), ng1 = tanhf(gin1 + r1 * ghn1);
        float h0 = xh[n * 68 + j0], h1 = xh[n * 68 + j0 + 1];
        float2 o;
        o.x = (1.f - z0) * ng0 + z0 * h0;
        o.y = (1.f - z1) * ng1 + z1 * h1;
        *(float2*)&hout[(size_t)node * 64 + j0] = o;
    }
}

// ---------------- fused Set2Set (3 iters) + head: one block per graph ----------------
__global__ __launch_bounds__(256) void k_s2s(const float* lbih, const float* lbhh,
                                             const float* b1, const float* W2,
                                             const float* b2, float* out) {
    int g = blockIdx.x, tid = threadIdx.x;
    int warp = tid >> 5, lane = tid & 31;
    __shared__ float qs[64], cs[64], qstar[128], gates[256];
    __shared__ float redm[8], reda[8], rsum[8][64];
    __shared__ float hid[64], lg[4];
    int s = g_gbeg[g], e = g_gbeg[g + 1];
    if (tid < 64) { qs[tid] = 0.f; cs[tid] = 0.f; }
    if (tid < 128) qstar[tid] = 0.f;
    __syncthreads();

    for (int it = 0; it < 3; it++) {
        float acc = lbih[tid] + lbhh[tid];
#pragma unroll 8
        for (int k = 0; k < 128; k++) acc += g_lWihT[k * 256 + tid] * qstar[k];
#pragma unroll 8
        for (int k = 0; k < 64; k++) acc += g_lWhhT[k * 256 + tid] * qs[k];
        gates[tid] = acc;
        __syncthreads();
        if (tid < 64) {
            float i = sigm(gates[tid]);
            float f = sigm(gates[64 + tid]);
            float gg = tanhf(gates[128 + tid]);
            float o = sigm(gates[192 + tid]);
            float c = f * cs[tid] + i * gg;
            cs[tid] = c;
            qs[tid] = o * tanhf(c);
        }
        __syncthreads();

        float q0 = qs[lane * 2], q1 = qs[lane * 2 + 1];
        float mymax = -1e30f;
        for (int n = s + warp; n < e; n += 8) {
            float2 hv = __ldg(&((const float2*)g_h)[(size_t)n * 32 + lane]);
            float p = hv.x * q0 + hv.y * q1;
            p += __shfl_xor_sync(0xffffffffu, p, 16);
            p += __shfl_xor_sync(0xffffffffu, p, 8);
            p += __shfl_xor_sync(0xffffffffu, p, 4);
            p += __shfl_xor_sync(0xffffffffu, p, 2);
            p += __shfl_xor_sync(0xffffffffu, p, 1);
            mymax = fmaxf(mymax, p);
        }
        if (lane == 0) redm[warp] = mymax;
        __syncthreads();
        float em = fmaxf(fmaxf(fmaxf(redm[0], redm[1]), fmaxf(redm[2], redm[3])),
                         fmaxf(fmaxf(redm[4], redm[5]), fmaxf(redm[6], redm[7])));
        float r0 = 0.f, r1 = 0.f, mysum = 0.f;
        for (int n = s + warp; n < e; n += 8) {
            float2 hv = __ldg(&((const float2*)g_h)[(size_t)n * 32 + lane]);
            float p = hv.x * q0 + hv.y * q1;
            p += __shfl_xor_sync(0xffffffffu, p, 16);
            p += __shfl_xor_sync(0xffffffffu, p, 8);
            p += __shfl_xor_sync(0xffffffffu, p, 4);
            p += __shfl_xor_sync(0xffffffffu, p, 2);
            p += __shfl_xor_sync(0xffffffffu, p, 1);
            float a = expf(p - em);
            mysum += a;
            r0 += a * hv.x;
            r1 += a * hv.y;
        }
        if (lane == 0) reda[warp] = mysum;
        rsum[warp][lane * 2] = r0;
        rsum[warp][lane * 2 + 1] = r1;
        __syncthreads();
        float asum = reda[0] + reda[1] + reda[2] + reda[3] +
                     reda[4] + reda[5] + reda[6] + reda[7];
        asum = fmaxf(asum, 1e-16f);
        if (tid < 64) {
            float rr = 0.f;
#pragma unroll
            for (int w = 0; w < 8; w++) rr += rsum[w][tid];
            qstar[64 + tid] = rr / asum;
            qstar[tid] = qs[tid];
        }
        __syncthreads();
    }

    if (tid < 64) {
        float acc = b1[tid];
#pragma unroll 8
        for (int k = 0; k < 128; k++) acc += g_W1T[k * 64 + tid] * qstar[k];
        hid[tid] = fmaxf(acc, 0.f);
    }
    __syncthreads();
    if (tid < 4) {
        float a = b2[tid];
        const float* w2 = W2 + tid * 64;
#pragma unroll 8
        for (int k = 0; k < 64; k++) a += w2[k] * hid[k];
        lg[tid] = a;
    }
    __syncthreads();
    if (tid < 4) {
        float m = fmaxf(fmaxf(lg[0], lg[1]), fmaxf(lg[2], lg[3]));
        float sum = expf(lg[0] - m) + expf(lg[1] - m) + expf(lg[2] - m) + expf(lg[3] - m);
        out[g * 4 + tid] = lg[tid] - m - logf(sum);
    }
}

// ---------------- launch ----------------
extern "C" void kernel_launch(void* const* d_in, const int* in_sizes, int n_in,
                              void* d_out, int out_size) {
    const float* x       = (const float*)d_in[0];
    const int*   ei      = (const int*)d_in[1];
    const int*   bt      = (const int*)d_in[2];
    const float* W_mlp   = (const float*)d_in[3];
    const float* b_mlp   = (const float*)d_in[4];
    const float* W_conv  = (const float*)d_in[5];
    const float* b_conv  = (const float*)d_in[6];
    const float* gWih    = (const float*)d_in[7];
    const float* gWhh    = (const float*)d_in[8];
    const float* gbih    = (const float*)d_in[9];
    const float* gbhh    = (const float*)d_in[10];
    const float* lWih    = (const float*)d_in[11];
    const float* lWhh    = (const float*)d_in[12];
    const float* lbih    = (const float*)d_in[13];
    const float* lbhh    = (const float*)d_in[14];
    const float* W1      = (const float*)d_in[15];
    const float* b1      = (const float*)d_in[16];
    const float* W2      = (const float*)d_in[17];
    const float* b2      = (const float*)d_in[18];
    float* out = (float*)d_out;

    static bool attr_set = false;
    if (!attr_set) {
        cudaFuncSetAttribute(k_gru4, cudaFuncAttributeMaxDynamicSharedMemorySize, GRU_SMEM);
        attr_set = true;
    }

    k_prepB<<<419, 256>>>(W_mlp, b_mlp, gWih, gbih, gWhh, W_conv, b_conv, lWih, lWhh, W1, ei, bt);
    k_hist<<<EE / 256, 256>>>(ei, bt);
    k_scan1<<<256, 256>>>();
    k_scan2<<<1, 256>>>();
    k_scan3<<<256, 256>>>();
    k_fill<<<EE / 256, 256>>>(ei);

    k_mlp2<<<NN / 16, 256>>>(x);

    k_gru4<<<NN / 64, 256, GRU_SMEM>>>(0, gbhh);
    k_gru4<<<NN / 64, 256, GRU_SMEM>>>(1, gbhh);

    k_s2s<<<BB, 256>>>(lbih, lbhh, b1, W2, b2, out);
}

// round 12
// speedup vs baseline: 1.1876x; 1.1876x over previous
#include <cuda_runtime.h>
#include <math.h>

#define NN 65536
#define EE 1048576
#define BB 256

// ---------------- device scratch (static globals; no allocation) ----------------
__device__ __align__(16) float g_h[NN * 64];      // node state h
__device__ __align__(16) float g_hB[NN * 64];     // ping-pong buffer
__device__ __align__(16) float g_agg[NN * 64];    // gathered sum of h[src]
__device__ __align__(16) float g_gix[NN * 192];   // W_ih[:,64:96]@x + b_ih
__device__ __align__(16) float g_Wx2[256 * 32];   // [o][k] o<64: W_mlp ; o>=64: W_ih x-part
__device__ float g_bx[256];
// GRU weights, [k][192] layout for coalesced smem staging
__device__ __align__(16) float g_WgA[64 * 192];   // Wcomb = W_ih_m @ W_conv (r,z,n)
__device__ __align__(16) float g_WgH[64 * 192];   // W_hh (r,z,n)
__device__ float g_bvec[192];                     // W_ih_m @ b_conv
// transposed Set2Set/head weights (coalesced: k-major)
__device__ __align__(16) float g_lWihT[128 * 256];
__device__ __align__(16) float g_lWhhT[64 * 256];
__device__ __align__(16) float g_W1T[128 * 64];
// CSR
__device__ int g_cnt[NN];
__device__ int g_off[NN];
__device__ int g_cur[NN];
__device__ float g_degf[NN];
__device__ int g_bsum[256];
__device__ int g_bpre[256];
__device__ int g_csr[EE];
// batch / graph ranges, attention cache
__device__ int g_bhist[256];
__device__ int g_gbeg[257];
__device__ float g_e[NN];
__device__ int g_is64e, g_is64b;

__device__ __forceinline__ float sigm(float x) { return 1.0f / (1.0f + expf(-x)); }

// packed fp32x2 fma (sm_103a)
__device__ __forceinline__ void ffma2(unsigned long long& d, unsigned long long a, unsigned long long b) {
    asm("fma.rn.f32x2 %0, %1, %2, %3;" : "=l"(d) : "l"(a), "l"(b), "l"(d));
}
__device__ __forceinline__ unsigned long long packdup(float x) {
    unsigned long long r;
    asm("mov.b64 %0, {%1, %1};" : "=l"(r) : "f"(x));
    return r;
}
__device__ __forceinline__ float lo2(unsigned long long v) { return __uint_as_float((unsigned)(v & 0xffffffffull)); }
__device__ __forceinline__ float hi2(unsigned long long v) { return __uint_as_float((unsigned)(v >> 32)); }

__device__ __forceinline__ int ld_idx(const int* p, int i, int is64) {
    return is64 ? p[2 * i] : p[i];
}

// ---------------- fused prep: dtype detect + all weight re-layouts + zeroing ----------------
__global__ void k_prepB(const float* W_mlp, const float* b_mlp,
                        const float* W_ih, const float* b_ih,
                        const float* W_hh, const float* W_conv, const float* b_conv,
                        const float* lWih, const float* lWhh, const float* W1,
                        const int* ei, const int* bt) {
    if (blockIdx.x == 0 && threadIdx.x < 32) {
        int lane = threadIdx.x;
        int v  = ei[2 * EE - 1 - 2 * lane];   // odd words near tail (int64 => 0)
        int vb = bt[NN - 1 - 2 * lane];       // batch sorted: tail != 0 for int32
        unsigned m  = __ballot_sync(0xffffffffu, v != 0);
        unsigned mb = __ballot_sync(0xffffffffu, vb != 0);
        if (lane == 0) { g_is64e = (m == 0u) ? 1 : 0; g_is64b = (mb == 0u) ? 1 : 0; }
    }
    int t = blockIdx.x * blockDim.x + threadIdx.x;
    if (t < 8192) {
        int o = t >> 5, k = t & 31;
        g_Wx2[t] = (o < 64) ? W_mlp[o * 32 + k] : W_ih[(o - 64) * 96 + 64 + k];
    } else if (t < 8448) {
        int o = t - 8192;
        g_bx[o] = (o < 64) ? b_mlp[o] : b_ih[o - 64];
    } else if (t < 20736) {
        int u = t - 8448;
        int g = u >> 12, j = (u >> 6) & 63, k = u & 63;
        const float* wr = W_ih + (g * 64 + j) * 96;
        float v = 0.f;
#pragma unroll 8
        for (int o = 0; o < 64; o++) v += wr[o] * W_conv[o * 64 + k];
        g_WgA[k * 192 + g * 64 + j] = v;
    } else if (t < 33024) {
        int u = t - 20736;
        int g = u >> 12, j = (u >> 6) & 63, k = u & 63;
        g_WgH[k * 192 + g * 64 + j] = W_hh[(g * 64 + j) * 64 + k];
    } else if (t < 33216) {
        int o = t - 33024;
        const float* wr = W_ih + o * 96;
        float v = 0.f;
#pragma unroll 8
        for (int o2 = 0; o2 < 64; o2++) v += wr[o2] * b_conv[o2];
        g_bvec[o] = v;
    } else if (t < 49600) {
        ((int4*)g_cnt)[t - 33216] = make_int4(0, 0, 0, 0);
    } else if (t < 49856) {
        g_bhist[t - 49600] = 0;
    } else if (t < 82624) {
        int u = t - 49856;
        int k = u >> 8, o = u & 255;
        g_lWihT[k * 256 + o] = lWih[o * 128 + k];
    } else if (t < 99008) {
        int u = t - 82624;
        int k = u >> 8, o = u & 255;
        g_lWhhT[k * 256 + o] = lWhh[o * 64 + k];
    } else if (t < 107200) {
        int u = t - 99008;
        int k = u >> 6, o = u & 63;
        g_W1T[k * 64 + o] = W1[o * 128 + k];
    }
}

// ---------------- histograms: edge dst (CSR) + batch (graph ranges) ----------------
__global__ void k_hist(const int* ei, const int* bt) {
    int t = blockIdx.x * 256 + threadIdx.x;
    int dst = ld_idx(ei, EE + t, g_is64e);
    atomicAdd(&g_cnt[dst], 1);
    if (t < NN) {
        int b = ld_idx(bt, t, g_is64b);
        atomicAdd(&g_bhist[b], 1);
    }
}
__global__ void k_scan1() {
    __shared__ int s[256];
    int tid = threadIdx.x;
    int i = blockIdx.x * 256 + tid;
    int v = g_cnt[i];
    s[tid] = v; __syncthreads();
    for (int d = 1; d < 256; d <<= 1) {
        int t = (tid >= d) ? s[tid - d] : 0; __syncthreads();
        s[tid] += t; __syncthreads();
    }
    g_off[i] = s[tid] - v;
    if (tid == 255) g_bsum[blockIdx.x] = s[255];
}
__global__ void k_scan2() {
    __shared__ int s[256];
    int tid = threadIdx.x;
    int v = g_bsum[tid];
    s[tid] = v; __syncthreads();
    for (int d = 1; d < 256; d <<= 1) {
        int t = (tid >= d) ? s[tid - d] : 0; __syncthreads();
        s[tid] += t; __syncthreads();
    }
    g_bpre[tid] = s[tid] - v;
    __syncthreads();
    int vb = g_bhist[tid];
    s[tid] = vb; __syncthreads();
    for (int d = 1; d < 256; d <<= 1) {
        int t = (tid >= d) ? s[tid - d] : 0; __syncthreads();
        s[tid] += t; __syncthreads();
    }
    g_gbeg[tid] = s[tid] - vb;
    if (tid == 255) g_gbeg[256] = s[255];
}
__global__ void k_scan3() {
    int i = blockIdx.x * 256 + threadIdx.x;
    int off = g_off[i] + g_bpre[blockIdx.x];
    g_off[i] = off;
    g_cur[i] = off;
    g_degf[i] = (float)g_cnt[i];
}
__global__ void k_fill(const int* ei) {
    int e = blockIdx.x * 256 + threadIdx.x;
    int is64 = g_is64e;
    int src = ld_idx(ei, e, is64);
    int dst = ld_idx(ei, EE + e, is64);
    int p = atomicAdd(&g_cur[dst], 1);
    g_csr[p] = src;
}

// ---------------- node MLP + gix precompute: [N,32]@[32,256] ----------------
__global__ __launch_bounds__(256) void k_mlp2(const float* x) {
    int o = threadIdx.x;
    int nb = blockIdx.x * 16;
    const ulonglong2* Wp = (const ulonglong2*)(g_Wx2 + o * 32);
    ulonglong2 w[8];
#pragma unroll
    for (int kk = 0; kk < 8; kk++) w[kk] = __ldg(&Wp[kk]);
    float bias = g_bx[o];
#pragma unroll 2
    for (int i = 0; i < 16; i++) {
        int n = nb + i;
        const ulonglong2* xr = (const ulonglong2*)(x + (size_t)n * 32);
        unsigned long long a0 = 0ull, a1 = 0ull;
#pragma unroll
        for (int kk = 0; kk < 8; kk++) {
            ulonglong2 v = __ldg(&xr[kk]);
            ffma2(a0, v.x, w[kk].x);
            ffma2(a1, v.y, w[kk].y);
        }
        float v = lo2(a0) + hi2(a0) + lo2(a1) + hi2(a1) + bias;
        if (o < 64) g_h[(size_t)n * 64 + o] = v;
        else        g_gix[(size_t)n * 192 + (o - 64)] = v;
    }
}

// ---------------- gather aggregation: agg[n] = sum_{e: dst=n} h[src] ----------------
__global__ __launch_bounds__(256) void k_gather(int step) {
    const float* hsrc = step ? g_hB : g_h;
    int warp = threadIdx.x >> 5, lane = threadIdx.x & 31;
    int node = blockIdx.x * 8 + warp;
    int beg = g_off[node], cnt = g_cnt[node];
    const float2* hb = (const float2*)hsrc;
    float ax = 0.f, ay = 0.f;
    int t = 0;
    for (; t + 4 <= cnt; t += 4) {
        int s0 = __ldg(&g_csr[beg + t]);
        int s1 = __ldg(&g_csr[beg + t + 1]);
        int s2 = __ldg(&g_csr[beg + t + 2]);
        int s3 = __ldg(&g_csr[beg + t + 3]);
        float2 v0 = __ldg(&hb[(size_t)s0 * 32 + lane]);
        float2 v1 = __ldg(&hb[(size_t)s1 * 32 + lane]);
        float2 v2 = __ldg(&hb[(size_t)s2 * 32 + lane]);
        float2 v3 = __ldg(&hb[(size_t)s3 * 32 + lane]);
        ax += v0.x + v1.x + v2.x + v3.x;
        ay += v0.y + v1.y + v2.y + v3.y;
    }
    for (; t < cnt; t++) {
        int s = __ldg(&g_csr[beg + t]);
        float2 v = __ldg(&hb[(size_t)s * 32 + lane]);
        ax += v.x; ay += v.y;
    }
    float2 out; out.x = ax; out.y = ay;
    ((float2*)g_agg)[(size_t)node * 32 + lane] = out;
}

// ---------------- fused GRU step (conv-fused, smem-staged, f32x2 over j-pairs) ----------------
#define GRU_SMEM ((64 * 68 * 2 + 64 * 192) * 4)
__global__ __launch_bounds__(256) void k_gru3(int step, const float* b_hh) {
    const float* hin = step ? g_hB : g_h;
    float* hout      = step ? g_h  : g_hB;
    extern __shared__ float sm[];
    float* Xa = sm;
    float* Xh = Xa + 64 * 68;
    float* Ws = Xh + 64 * 68;

    int tid = threadIdx.x;
    int nb = blockIdx.x * 64;

    for (int i = tid; i < 64 * 16; i += 256) {
        int n = i >> 4, kq = i & 15;
        float4 va = *(const float4*)&g_agg[(size_t)(nb + n) * 64 + kq * 4];
        float4 vh = *(const float4*)&hin[(size_t)(nb + n) * 64 + kq * 4];
        *(float4*)&Xa[n * 68 + kq * 4] = va;
        *(float4*)&Xh[n * 68 + kq * 4] = vh;
    }
    for (int i = tid; i < 64 * 192 / 4; i += 256)
        ((float4*)Ws)[i] = ((const float4*)g_WgA)[i];
    __syncthreads();

    int tg = tid & 31;
    int tn = tid >> 5;
    const float* xa = Xa + (tn * 8) * 68;
    const float* xh = Xh + (tn * 8) * 68;

    unsigned long long gia[3][8], gha[3][8];
#pragma unroll
    for (int g = 0; g < 3; g++)
#pragma unroll
        for (int n = 0; n < 8; n++) { gia[g][n] = 0ull; gha[g][n] = 0ull; }

#pragma unroll 4
    for (int k = 0; k < 64; k++) {
        unsigned long long w0 = *(const unsigned long long*)&Ws[k * 192 + tg * 2];
        unsigned long long w1 = *(const unsigned long long*)&Ws[k * 192 + 64 + tg * 2];
        unsigned long long w2 = *(const unsigned long long*)&Ws[k * 192 + 128 + tg * 2];
#pragma unroll
        for (int n = 0; n < 8; n++) {
            unsigned long long xd = packdup(xa[n * 68 + k]);
            ffma2(gia[0][n], xd, w0);
            ffma2(gia[1][n], xd, w1);
            ffma2(gia[2][n], xd, w2);
        }
    }
    __syncthreads();
    for (int i = tid; i < 64 * 192 / 4; i += 256)
        ((float4*)Ws)[i] = ((const float4*)g_WgH)[i];
    __syncthreads();
#pragma unroll 4
    for (int k = 0; k < 64; k++) {
        unsigned long long w0 = *(const unsigned long long*)&Ws[k * 192 + tg * 2];
        unsigned long long w1 = *(const unsigned long long*)&Ws[k * 192 + 64 + tg * 2];
        unsigned long long w2 = *(const unsigned long long*)&Ws[k * 192 + 128 + tg * 2];
#pragma unroll
        for (int n = 0; n < 8; n++) {
            unsigned long long xd = packdup(xh[n * 68 + k]);
            ffma2(gha[0][n], xd, w0);
            ffma2(gha[1][n], xd, w1);
            ffma2(gha[2][n], xd, w2);
        }
    }

    int j0 = tg * 2;
    float2 bh_r = *(const float2*)&b_hh[j0];
    float2 bh_z = *(const float2*)&b_hh[64 + j0];
    float2 bh_n = *(const float2*)&b_hh[128 + j0];
    float2 bv_r = *(const float2*)&g_bvec[j0];
    float2 bv_z = *(const float2*)&g_bvec[64 + j0];
    float2 bv_n = *(const float2*)&g_bvec[128 + j0];
#pragma unroll
    for (int n = 0; n < 8; n++) {
        int node = nb + tn * 8 + n;
        float degf = g_degf[node];
        const float* gx = g_gix + (size_t)node * 192;
        float2 gx_r = *(const float2*)&gx[j0];
        float2 gx_z = *(const float2*)&gx[64 + j0];
        float2 gx_n = *(const float2*)&gx[128 + j0];

        float gir0 = lo2(gia[0][n]) + gx_r.x + degf * bv_r.x;
        float gir1 = hi2(gia[0][n]) + gx_r.y + degf * bv_r.y;
        float giz0 = lo2(gia[1][n]) + gx_z.x + degf * bv_z.x;
        float giz1 = hi2(gia[1][n]) + gx_z.y + degf * bv_z.y;
        float gin0 = lo2(gia[2][n]) + gx_n.x + degf * bv_n.x;
        float gin1 = hi2(gia[2][n]) + gx_n.y + degf * bv_n.y;
        float ghr0 = lo2(gha[0][n]) + bh_r.x;
        float ghr1 = hi2(gha[0][n]) + bh_r.y;
        float ghz0 = lo2(gha[1][n]) + bh_z.x;
        float ghz1 = hi2(gha[1][n]) + bh_z.y;
        float ghn0 = lo2(gha[2][n]) + bh_n.x;
        float ghn1 = hi2(gha[2][n]) + bh_n.y;

        float r0 = sigm(gir0 + ghr0), r1 = sigm(gir1 + ghr1);
        float z0 = sigm(giz0 + ghz0), z1 = sigm(giz1 + ghz1);
        float ng0 = tanhf(gin0 + r0 * ghn0), ng1 = tanhf(gin1 + r1 * ghn1);
        float h0 = xh[n * 68 + j0], h1 = xh[n * 68 + j0 + 1];
        float2 o;
        o.x = (1.f - z0) * ng0 + z0 * h0;
        o.y = (1.f - z1) * ng1 + z1 * h1;
        *(float2*)&hout[(size_t)node * 64 + j0] = o;
    }
}

// ---------------- fused Set2Set (3 iters) + head: one block per graph ----------------
// pass 1 caches e[n] to g_e (so pass 2 skips the dot+shfl); both passes unrolled x2
// for independent latency chains.
__global__ __launch_bounds__(256) void k_s2s(const float* lbih, const float* lbhh,
                                             const float* b1, const float* W2,
                                             const float* b2, float* out) {
    int g = blockIdx.x, tid = threadIdx.x;
    int warp = tid >> 5, lane = tid & 31;
    __shared__ float qs[64], cs[64], qstar[128], gates[256];
    __shared__ float redm[8], reda[8], rsum[8][64];
    __shared__ float hid[64], lg[4];
    int s = g_gbeg[g], e = g_gbeg[g + 1];
    if (tid < 64) { qs[tid] = 0.f; cs[tid] = 0.f; }
    if (tid < 128) qstar[tid] = 0.f;
    __syncthreads();

    for (int it = 0; it < 3; it++) {
        float acc = lbih[tid] + lbhh[tid];
#pragma unroll 8
        for (int k = 0; k < 128; k++) acc += g_lWihT[k * 256 + tid] * qstar[k];
#pragma unroll 8
        for (int k = 0; k < 64; k++) acc += g_lWhhT[k * 256 + tid] * qs[k];
        gates[tid] = acc;
        __syncthreads();
        if (tid < 64) {
            float i = sigm(gates[tid]);
            float f = sigm(gates[64 + tid]);
            float gg = tanhf(gates[128 + tid]);
            float o = sigm(gates[192 + tid]);
            float c = f * cs[tid] + i * gg;
            cs[tid] = c;
            qs[tid] = o * tanhf(c);
        }
        __syncthreads();

        float q0 = qs[lane * 2], q1 = qs[lane * 2 + 1];
        // pass 1: e[n] = <h_n, q> cached to g_e; segment max (x2 unroll)
        float mymax = -1e30f;
        for (int n = s + warp; n < e; n += 16) {
            int n2 = n + 8;
            float2 hv = __ldg(&((const float2*)g_h)[(size_t)n * 32 + lane]);
            float p = hv.x * q0 + hv.y * q1;
            float p2 = 0.f;
            if (n2 < e) {
                float2 hv2 = __ldg(&((const float2*)g_h)[(size_t)n2 * 32 + lane]);
                p2 = hv2.x * q0 + hv2.y * q1;
            }
#pragma unroll
            for (int d = 16; d >= 1; d >>= 1) {
                p  += __shfl_xor_sync(0xffffffffu, p, d);
                p2 += __shfl_xor_sync(0xffffffffu, p2, d);
            }
            if (lane == 0) g_e[n] = p;
            mymax = fmaxf(mymax, p);
            if (n2 < e) {
                if (lane == 0) g_e[n2] = p2;
                mymax = fmaxf(mymax, p2);
            }
        }
        if (lane == 0) redm[warp] = mymax;
        __syncthreads();   // also makes g_e writes visible block-wide
        float em = fmaxf(fmaxf(fmaxf(redm[0], redm[1]), fmaxf(redm[2], redm[3])),
                         fmaxf(fmaxf(redm[4], redm[5]), fmaxf(redm[6], redm[7])));
        // pass 2: a = exp(e - em); asum; r = sum a*h (x2 unroll, no recompute)
        float r0 = 0.f, r1 = 0.f, mysum = 0.f;
        for (int n = s + warp; n < e; n += 16) {
            int n2 = n + 8;
            float a = expf(__ldg(&g_e[n]) - em);
            float2 hv = __ldg(&((const float2*)g_h)[(size_t)n * 32 + lane]);
            mysum += a; r0 += a * hv.x; r1 += a * hv.y;
            if (n2 < e) {
                float a2 = expf(__ldg(&g_e[n2]) - em);
                float2 hv2 = __ldg(&((const float2*)g_h)[(size_t)n2 * 32 + lane]);
                mysum += a2; r0 += a2 * hv2.x; r1 += a2 * hv2.y;
            }
        }
        if (lane == 0) reda[warp] = mysum;
        rsum[warp][lane * 2] = r0;
        rsum[warp][lane * 2 + 1] = r1;
        __syncthreads();
        float asum = reda[0] + reda[1] + reda[2] + reda[3] +
                     reda[4] + reda[5] + reda[6] + reda[7];
        asum = fmaxf(asum, 1e-16f);
        if (tid < 64) {
            float rr = 0.f;
#pragma unroll
            for (int w = 0; w < 8; w++) rr += rsum[w][tid];
            qstar[64 + tid] = rr / asum;
            qstar[tid] = qs[tid];
        }
        __syncthreads();
    }

    if (tid < 64) {
        float acc = b1[tid];
#pragma unroll 8
        for (int k = 0; k < 128; k++) acc += g_W1T[k * 64 + tid] * qstar[k];
        hid[tid] = fmaxf(acc, 0.f);
    }
    __syncthreads();
    if (tid < 4) {
        float a = b2[tid];
        const float* w2 = W2 + tid * 64;
#pragma unroll 8
        for (int k = 0; k < 64; k++) a += w2[k] * hid[k];
        lg[tid] = a;
    }
    __syncthreads();
    if (tid < 4) {
        float m = fmaxf(fmaxf(lg[0], lg[1]), fmaxf(lg[2], lg[3]));
        float sum = expf(lg[0] - m) + expf(lg[1] - m) + expf(lg[2] - m) + expf(lg[3] - m);
        out[g * 4 + tid] = lg[tid] - m - logf(sum);
    }
}

// ---------------- launch ----------------
extern "C" void kernel_launch(void* const* d_in, const int* in_sizes, int n_in,
                              void* d_out, int out_size) {
    const float* x       = (const float*)d_in[0];
    const int*   ei      = (const int*)d_in[1];
    const int*   bt      = (const int*)d_in[2];
    const float* W_mlp   = (const float*)d_in[3];
    const float* b_mlp   = (const float*)d_in[4];
    const float* W_conv  = (const float*)d_in[5];
    const float* b_conv  = (const float*)d_in[6];
    const float* gWih    = (const float*)d_in[7];
    const float* gWhh    = (const float*)d_in[8];
    const float* gbih    = (const float*)d_in[9];
    const float* gbhh    = (const float*)d_in[10];
    const float* lWih    = (const float*)d_in[11];
    const float* lWhh    = (const float*)d_in[12];
    const float* lbih    = (const float*)d_in[13];
    const float* lbhh    = (const float*)d_in[14];
    const float* W1      = (const float*)d_in[15];
    const float* b1      = (const float*)d_in[16];
    const float* W2      = (const float*)d_in[17];
    const float* b2      = (const float*)d_in[18];
    float* out = (float*)d_out;

    static cudaStream_t sB = nullptr;
    static cudaEvent_t evA = nullptr, evB = nullptr;
    static bool init_done = false;
    if (!init_done) {
        cudaFuncSetAttribute(k_gru3, cudaFuncAttributeMaxDynamicSharedMemorySize, GRU_SMEM);
        cudaStreamCreateWithFlags(&sB, cudaStreamNonBlocking);
        cudaEventCreateWithFlags(&evA, cudaEventDisableTiming);
        cudaEventCreateWithFlags(&evB, cudaEventDisableTiming);
        init_done = true;
    }

    k_prepB<<<419, 256>>>(W_mlp, b_mlp, gWih, gbih, gWhh, W_conv, b_conv, lWih, lWhh, W1, ei, bt);

    // fork: CSR chain on side stream, node MLP on main stream
    cudaEventRecord(evA, 0);
    cudaStreamWaitEvent(sB, evA, 0);
    k_hist<<<EE / 256, 256, 0, sB>>>(ei, bt);
    k_scan1<<<256, 256, 0, sB>>>();
    k_scan2<<<1, 256, 0, sB>>>();
    k_scan3<<<256, 256, 0, sB>>>();
    k_fill<<<EE / 256, 256, 0, sB>>>(ei);
    cudaEventRecord(evB, sB);

    k_mlp2<<<NN / 16, 256>>>(x);

    // join
    cudaStreamWaitEvent(0, evB, 0);

    k_gather<<<NN / 8, 256>>>(0);
    k_gru3<<<NN / 64, 256, GRU_SMEM>>>(0, gbhh);
    k_gather<<<NN / 8, 256>>>(1);
    k_gru3<<<NN / 64, 256, GRU_SMEM>>>(1, gbhh);

    k_s2s<<<BB, 256>>>(lbih, lbhh, b1, W2, b2, out);
}